// round 7
// baseline (speedup 1.0000x reference)
#include <cuda_runtime.h>
#include <cuda_bf16.h>
#include <cstdint>

typedef unsigned long long u64;

// Problem constants
#define B_   16          // batch
#define N_   1152        // primary caps
#define DP   8           // dim primary
#define M_   10          // digit caps
#define DD   16          // dim digit
#define CH   16          // n per chunk
#define NC   (N_ / CH)   // 72 chunks
#define SSTR 132         // float stride per nn row (16B-aligned rows)
#define RP   260         // float stride for transpose tile rows

// Partials [m][chunk][b*16+d]; counter zero-init, inc wraps -> self-reset each launch
__device__ float    g_partial[M_ * NC * B_ * DD];
__device__ unsigned g_ctr[M_];

__device__ __forceinline__ void fma2(u64& acc, u64 a, u64 b) {
    asm("fma.rn.f32x2 %0, %1, %2, %0;" : "+l"(acc) : "l"(a), "l"(b));
}

__device__ __forceinline__ void cp16(uint32_t s, const void* g) {
    asm volatile("cp.async.cg.shared.global [%0], [%1], 16;" :: "r"(s), "l"(g));
}

__device__ __forceinline__ uint32_t s2u(const void* p) {
    uint32_t a;
    asm("{ .reg .u64 t; cvta.to.shared.u64 t, %1; cvt.u32.u64 %0, t; }" : "=r"(a) : "l"(p));
    return a;
}

__global__ __launch_bounds__(256) void digitcaps_fused(
    const float* __restrict__ u,   // [B, N, DP]
    const float* __restrict__ W,   // [M, N, DD, DP]
    const float* __restrict__ Bp,  // [M, 1, N]
    float* __restrict__ out)       // [B, M, DD]
{
    __shared__ __align__(16) float smem_raw[2 * CH * SSTR];  // 16896 B; overlay tile 16*260*4 = 16640 B
    __shared__ float sBp[CH];
    __shared__ unsigned sLast;

    float* sW = smem_raw;              // [nn][d*8+p]
    float* sU = sW + CH * SSTR;        // [nn][b*8+p]
    float* sP = smem_raw;              // overlay after compute: [nn][260]

    const int chunk = blockIdx.x;      // 0..71
    const int m     = blockIdx.y;      // 0..9
    const int tid   = threadIdx.x;
    const int n0    = chunk * CH;

    // Bp (broadcast loads, overlap with async copies)
    if (tid < CH) sBp[tid] = 1.0f + __ldg(&Bp[m * N_ + n0 + tid]);

    // ---- async stage W: 16 nn * 128 floats = 512 x 16B chunks (2/thread)
    {
        const float* gw = W + ((size_t)m * N_ + n0) * (DD * DP);
        #pragma unroll
        for (int r = 0; r < 2; ++r) {
            const int f  = tid + r * 256;   // 0..511
            const int nn = f >> 5;          // 32 chunks per nn
            const int k4 = (f & 31) * 4;
            cp16(s2u(&sW[nn * SSTR + k4]), gw + (size_t)nn * 128 + k4);
        }
    }
    // ---- async stage u transposed to [nn][b*8+p]: 512 x 16B chunks (2/thread)
    {
        #pragma unroll
        for (int r = 0; r < 2; ++r) {
            const int f   = tid + r * 256;
            const int b   = f >> 5;         // 32 chunks per b
            const int rem = f & 31;
            const int nn  = rem >> 1;
            const int ph  = (rem & 1) * 4;
            cp16(s2u(&sU[nn * SSTR + b * 8 + ph]),
                 u + ((size_t)b * N_ + n0 + nn) * DP + ph);
        }
    }
    asm volatile("cp.async.commit_group;" ::: "memory");
    asm volatile("cp.async.wait_group 0;" ::: "memory");
    __syncthreads();

    // ---- compute: thread (nn_g, bg, dg) -> 4b x 4d for one nn, packed f32x2 over p
    const int nn_g = tid & 15;
    const int bg   = (tid >> 4) & 3;
    const int dg   = tid >> 6;

    const float sc = sBp[nn_g];
    const float* uS = &sU[nn_g * SSTR + bg * 32];
    const float* wS = &sW[nn_g * SSTR + dg * 32];

    ulonglong2 U0[4], U1[4];
    #pragma unroll
    for (int i = 0; i < 4; ++i) {
        U0[i] = *(const ulonglong2*)(uS + i * 8);      // (p0,p1),(p2,p3)
        U1[i] = *(const ulonglong2*)(uS + i * 8 + 4);  // (p4,p5),(p6,p7)
    }

    float S[4][4];
    #pragma unroll
    for (int j = 0; j < 4; ++j) {
        const ulonglong2 w0 = *(const ulonglong2*)(wS + j * 8);
        const ulonglong2 w1 = *(const ulonglong2*)(wS + j * 8 + 4);
        #pragma unroll
        for (int i = 0; i < 4; ++i) {
            u64 a = 0ull;
            fma2(a, U0[i].x, w0.x);
            fma2(a, U0[i].y, w0.y);
            fma2(a, U1[i].x, w1.x);
            fma2(a, U1[i].y, w1.y);
            const float lo = __uint_as_float((unsigned)(a & 0xffffffffu));
            const float hi = __uint_as_float((unsigned)(a >> 32));
            S[i][j] = sc * (lo + hi);
        }
    }

    // ---- smem transpose reduce over the 16 nn rows
    __syncthreads();   // staging reads done before overlay write
    {
        float* row = &sP[nn_g * RP];
        #pragma unroll
        for (int i = 0; i < 4; ++i) {
            const int bd = (bg * 4 + i) * DD + dg * 4;
            *(float4*)(row + bd) = make_float4(S[i][0], S[i][1], S[i][2], S[i][3]);
        }
    }
    __syncthreads();

    float Sp = sP[tid];
    #pragma unroll
    for (int nn = 1; nn < 16; ++nn) Sp += sP[nn * RP + tid];

    // coalesced partial write [m][chunk][tid]
    g_partial[((size_t)m * NC + chunk) * (B_ * DD) + tid] = Sp;

    // ---- last CTA per m: one acq_rel atomic replaces the threadfences
    __syncthreads();   // all STGs happen-before tid0's release
    if (tid == 0) {
        unsigned old;
        asm volatile("atom.acq_rel.gpu.global.inc.u32 %0, [%1], %2;"
                     : "=r"(old) : "l"(&g_ctr[m]), "r"((unsigned)(NC - 1)) : "memory");
        sLast = old;
    }
    __syncthreads();
    if (sLast != NC - 1) return;

    const float* pm = &g_partial[(size_t)m * NC * (B_ * DD)];
    float Sv = 0.f;
    #pragma unroll
    for (int c = 0; c < NC; ++c)
        Sv += __ldcg(pm + c * (B_ * DD) + tid);

    float n2 = Sv * Sv;
    #pragma unroll
    for (int off = 8; off >= 1; off >>= 1)
        n2 += __shfl_xor_sync(0xFFFFFFFFu, n2, off, 16);

    const float norm  = sqrtf(n2);
    const float coef  = 1.0f - expf(-norm);
    const float scale = coef / (norm + 1e-7f);

    const int b = tid >> 4;
    const int d = tid & 15;
    out[((size_t)b * M_ + m) * DD + d] = Sv * scale;
}

extern "C" void kernel_launch(void* const* d_in, const int* in_sizes, int n_in,
                              void* d_out, int out_size)
{
    const float* u  = (const float*)d_in[0];   // primary_caps [16,1152,8]
    const float* W  = (const float*)d_in[1];   // W [10,1152,16,8]
    const float* Bp = (const float*)d_in[2];   // B_prior [10,1,1152]
    float* out = (float*)d_out;                // [16,10,16]

    dim3 grid(NC, M_);
    digitcaps_fused<<<grid, 256>>>(u, W, Bp, out);
}